// round 16
// baseline (speedup 1.0000x reference)
#include <cuda_runtime.h>
#include <cuda_fp16.h>
#include <cstdint>

// ---------------------------------------------------------------------------
// Problem constants
// ---------------------------------------------------------------------------
#define Bc    4
#define Cc    256
#define Hc    56
#define Wc    56
#define Gc    16
#define Kc    7
#define TNUM  256
#define HW    (Hc * Wc)          // 3136
#define CG    (Cc / Gc)          // 16
#define KK    (Kc * Kc)          // 49
#define GK    (Gc * KK)          // 784
#define EPSc  1e-5f
#define KDIM  256

// ---------------------------------------------------------------------------
// Scratch (no runtime allocation allowed)
// ---------------------------------------------------------------------------
__device__ __half g_xh[Bc * Cc * HW];
__device__ __half g_xl[Bc * Cc * HW];
__device__ __half g_th[Bc * TNUM * HW];
__device__ __half g_tl[Bc * TNUM * HW];
__device__ __half g_w1h[TNUM * Cc];
__device__ __half g_w1l[TNUM * Cc];
__device__ __half g_w2h[GK * KDIM];
__device__ __half g_w2l[GK * KDIM];
__device__ float  g_ker[Bc * GK * HW];

// ---------------------------------------------------------------------------
// helpers
// ---------------------------------------------------------------------------
__device__ __forceinline__ void split2(float x, float y,
                                       uint32_t& hi, uint32_t& lo) {
    __half hx = __float2half_rn(x);
    __half hy = __float2half_rn(y);
    __half lx = __float2half_rn(x - __half2float(hx));
    __half ly = __float2half_rn(y - __half2float(hy));
    hi = (uint32_t)__half_as_ushort(hx) | ((uint32_t)__half_as_ushort(hy) << 16);
    lo = (uint32_t)__half_as_ushort(lx) | ((uint32_t)__half_as_ushort(ly) << 16);
}

__device__ __forceinline__ uint32_t smem_u32(const void* p) {
    uint32_t a;
    asm("{ .reg .u64 t; cvta.to.shared.u64 t, %1; cvt.u32.u64 %0, t; }"
        : "=r"(a) : "l"(p));
    return a;
}

// non-volatile — register-only, no side effects
#define MMA16816(Cr, Ar, B0, B1)                                           \
    asm("mma.sync.aligned.m16n8k16.row.col.f32.f16.f16.f32 "              \
        "{%0,%1,%2,%3}, {%4,%5,%6,%7}, {%8,%9}, {%0,%1,%2,%3};"           \
        : "+f"((Cr)[0]), "+f"((Cr)[1]), "+f"((Cr)[2]), "+f"((Cr)[3])       \
        : "r"((Ar)[0]), "r"((Ar)[1]), "r"((Ar)[2]), "r"((Ar)[3]),          \
          "r"(B0), "r"(B1))

#define LDSM4(R, addr)                                                     \
    asm volatile("ldmatrix.sync.aligned.m8n8.x4.shared.b16 "               \
        "{%0,%1,%2,%3}, [%4];"                                             \
        : "=r"((R)[0]), "=r"((R)[1]), "=r"((R)[2]), "=r"((R)[3])           \
        : "r"(addr))

#define LDSM4T(R, addr)                                                    \
    asm volatile("ldmatrix.sync.aligned.m8n8.x4.trans.shared.b16 "         \
        "{%0,%1,%2,%3}, [%4];"                                             \
        : "=r"((R)[0]), "=r"((R)[1]), "=r"((R)[2]), "=r"((R)[3])           \
        : "r"(addr))

#define CP_ASYNC16(dst, src, sz)                                           \
    asm volatile("cp.async.cg.shared.global [%0], [%1], 16, %2;"           \
        :: "r"(dst), "l"(src), "r"(sz))
#define CP_COMMIT() asm volatile("cp.async.commit_group;")

// ---------------------------------------------------------------------------
// fp32 -> fp16 hi/lo split (elementwise, float4-vectorized)
// ---------------------------------------------------------------------------
__global__ __launch_bounds__(256)
void split_kernel(const float4* __restrict__ src,
                  uint2* __restrict__ hi, uint2* __restrict__ lo, int n4)
{
    int i = blockIdx.x * blockDim.x + threadIdx.x;
    if (i >= n4) return;
    float4 v = src[i];
    uint32_t h0, l0, h1, l1;
    split2(v.x, v.y, h0, l0);
    split2(v.z, v.w, h1, l1);
    hi[i] = make_uint2(h0, h1);
    lo[i] = make_uint2(l0, l1);
}

// ---------------------------------------------------------------------------
// Split-fp16 HMMA GEMM — R13 structure (best known), verbatim.
//   D[M,N] = A[M,K]*B[K,N], K=256.  3 MMAs per k-step in 3 passes.
// Block: 256 thr (8 warps, 4Mx2N), tile 128x64, BK=32, 2-stage ring, 3 CTA/SM.
// ---------------------------------------------------------------------------
#define BMg 128
#define BNg 64
#define BKg 32
#define NCH (KDIM / BKg)          // 8
#define NST 2
#define PKA 40                    // A smem pitch (halves)
#define PKB 72                    // B smem pitch (halves)
#define A_BY (BMg * PKA * 2)      // 10240
#define B_BY (BKg * PKB * 2)      // 4608
#define STG_BY (2 * A_BY + 2 * B_BY)   // 29696
#define SMEM_TOT (NST * STG_BY)        // 59392

template <int EPI>
__global__ __launch_bounds__(256, 3)
void gemm_split_kernel(const __half* __restrict__ Ahi,  // [M][K]
                       const __half* __restrict__ Alo,
                       const __half* __restrict__ Bhi,  // [batch][K][N]
                       const __half* __restrict__ Blo,
                       float* __restrict__ Cf,
                       __half* __restrict__ Chi,
                       __half* __restrict__ Clo,
                       int M, int Nfull,
                       const float* __restrict__ bias,
                       const float* __restrict__ gamma,
                       const float* __restrict__ beta,
                       const float* __restrict__ mean,
                       const float* __restrict__ var,
                       const float* __restrict__ prelu_a)
{
    extern __shared__ __align__(16) char smem[];
    const uint32_t sbase = smem_u32(smem);

    const int tid  = threadIdx.x;
    const int lane = tid & 31;
    const int wid  = tid >> 5;
    const int wm   = wid & 3;
    const int wn   = wid >> 2;
    const int lane15 = lane & 15;
    const int hi8    = (lane & 16) >> 1;
    const int g    = lane >> 2;
    const int t2   = (lane & 3) * 2;

    const int rowBase = blockIdx.x * BMg;
    const int colBase = blockIdx.y * BNg;
    const int batch   = blockIdx.z;
    const __half* BhiP = Bhi + (size_t)batch * KDIM * Nfull;
    const __half* BloP = Blo + (size_t)batch * KDIM * Nfull;

    const int a_idx0 = tid;
    const int a_idx1 = tid + 256;
    const int b_kr = tid >> 3;
    const int b_nq = tid & 7;

    auto issue = [&](int ch, int s) {
        const int kc = ch * BKg;
        const uint32_t stg = sbase + s * STG_BY;
#pragma unroll
        for (int i = 0; i < 2; i++) {
            const int idx = i ? a_idx1 : a_idx0;
            const int row = idx >> 2;
            const int kq  = idx & 3;
            const int gm  = rowBase + row;
            const uint32_t sz = (gm < M) ? 16u : 0u;
            const int gmc = (gm < M) ? gm : 0;
            const uint32_t adst = stg + row * (PKA * 2) + kq * 16;
            const size_t  asrc = (size_t)gmc * KDIM + kc + kq * 8;
            CP_ASYNC16(adst,        Ahi + asrc, sz);
            CP_ASYNC16(adst + A_BY, Alo + asrc, sz);
        }
        const uint32_t bdst = stg + 2 * A_BY + b_kr * (PKB * 2) + b_nq * 16;
        const size_t  bsrc = (size_t)(kc + b_kr) * Nfull + colBase + b_nq * 8;
        CP_ASYNC16(bdst,        BhiP + bsrc, 16u);
        CP_ASYNC16(bdst + B_BY, BloP + bsrc, 16u);
        CP_COMMIT();
    };

    float acc[2][4][4];
#pragma unroll
    for (int mt = 0; mt < 2; mt++)
#pragma unroll
        for (int nt = 0; nt < 4; nt++)
#pragma unroll
            for (int i = 0; i < 4; i++) acc[mt][nt][i] = 0.f;

    issue(0, 0);

    for (int c = 0; c < NCH; c++) {
        asm volatile("cp.async.wait_group 0;");
        __syncthreads();
        if (c + 1 < NCH) issue(c + 1, (c + 1) % NST);

        const int s = c % NST;
        const uint32_t aHiB = sbase + s * STG_BY;
        const uint32_t aLoB = aHiB + A_BY;
        const uint32_t bHiB = aHiB + 2 * A_BY;
        const uint32_t bLoB = bHiB + B_BY;

#pragma unroll
        for (int ks = 0; ks < 2; ks++) {
            const int k0 = ks * 16;
            uint32_t ah[2][4], al[2][4], bh[2][4], bl[2][4];
#pragma unroll
            for (int mt = 0; mt < 2; mt++) {
                int row = wm * 32 + mt * 16 + lane15;
                uint32_t off = row * (PKA * 2) + (k0 + hi8) * 2;
                LDSM4(ah[mt], aHiB + off);
                LDSM4(al[mt], aLoB + off);
            }
#pragma unroll
            for (int nb = 0; nb < 2; nb++) {
                int nn   = wn * 32 + nb * 16 + hi8;
                int krow = k0 + lane15;
                uint32_t off = krow * (PKB * 2) + nn * 2;
                LDSM4T(bh[nb], bHiB + off);
                LDSM4T(bl[nb], bLoB + off);
            }
#pragma unroll
            for (int nb = 0; nb < 2; nb++)
#pragma unroll
                for (int ng = 0; ng < 2; ng++)
#pragma unroll
                    for (int mt = 0; mt < 2; mt++)
                        MMA16816(acc[mt][nb * 2 + ng], ah[mt],
                                 bh[nb][2 * ng], bh[nb][2 * ng + 1]);
#pragma unroll
            for (int nb = 0; nb < 2; nb++)
#pragma unroll
                for (int ng = 0; ng < 2; ng++)
#pragma unroll
                    for (int mt = 0; mt < 2; mt++)
                        MMA16816(acc[mt][nb * 2 + ng], ah[mt],
                                 bl[nb][2 * ng], bl[nb][2 * ng + 1]);
#pragma unroll
            for (int nb = 0; nb < 2; nb++)
#pragma unroll
                for (int ng = 0; ng < 2; ng++)
#pragma unroll
                    for (int mt = 0; mt < 2; mt++)
                        MMA16816(acc[mt][nb * 2 + ng], al[mt],
                                 bh[nb][2 * ng], bh[nb][2 * ng + 1]);
        }
    }

    // ---- epilogue ----
#pragma unroll
    for (int mt = 0; mt < 2; mt++) {
        int r0 = rowBase + wm * 32 + mt * 16 + g;
#pragma unroll
        for (int half_ = 0; half_ < 2; half_++) {
            int rr = r0 + half_ * 8;
            if (rr >= M) continue;
            float bb = bias[rr];
            float sc = 0.f, mn = 0.f, bt = 0.f, aa = 0.f;
            if (EPI == 1) {
                sc = gamma[rr] * rsqrtf(var[rr] + EPSc);
                mn = mean[rr];
                bt = beta[rr];
                aa = prelu_a[0];
            }
#pragma unroll
            for (int nt = 0; nt < 4; nt++) {
                int col = colBase + wn * 32 + nt * 8 + t2;
                float v0 = acc[mt][nt][half_ * 2 + 0] + bb;
                float v1 = acc[mt][nt][half_ * 2 + 1] + bb;
                if (EPI == 1) {
                    v0 = (v0 - mn) * sc + bt;
                    v1 = (v1 - mn) * sc + bt;
                    v0 = v0 > 0.f ? v0 : aa * v0;
                    v1 = v1 > 0.f ? v1 : aa * v1;
                    uint32_t hw_, lw_;
                    split2(v0, v1, hw_, lw_);
                    size_t idx = ((size_t)batch * M + rr) * Nfull + col;
                    *(uint32_t*)(Chi + idx) = hw_;
                    *(uint32_t*)(Clo + idx) = lw_;
                } else {
                    size_t idx = ((size_t)batch * M + rr) * Nfull + col;
                    *(float2*)(Cf + idx) = make_float2(v0, v1);
                }
            }
        }
    }
}

// ---------------------------------------------------------------------------
// Involution — vectorized rewrite.
// Thread = 4-pixel quad x 4 channels (224 active). Window rows load as
// LDS.128/.128/.64 (10 floats for 4 outputs); ker taps staged in smem so a
// tap-quad is ONE LDS.128 shared by 4 channels. 5.9x fewer LDS ops.
// ---------------------------------------------------------------------------
#define TH2   4
#define HR2   (TH2 + 6)           // 10 halo rows
#define HC2   62                  // halo cols used
#define HP2   68                  // xs row pitch (floats) — bank stagger
#define XS_CH (HR2 * HP2)         // 680 floats per channel
#define XS_FL (CG * XS_CH)        // 10880
#define PIX   (TH2 * Wc)          // 224 pixels per block
#define KS_FL (KK * PIX)          // 10976
#define INV_SMEM ((XS_FL + KS_FL) * 4)   // 87424 bytes

__global__ __launch_bounds__(256)
void involution_kernel(const float* __restrict__ x,
                       const float* __restrict__ ker,
                       float* __restrict__ out)
{
    extern __shared__ __align__(16) float sm[];
    float* xs = sm;                 // [CG][HR2][HP2]
    float* ks = sm + XS_FL;         // [KK][PIX]

    const int tileRow = blockIdx.x;
    const int g = blockIdx.y;
    const int b = blockIdx.z;
    const int tid = threadIdx.x;
    const int h0 = tileRow * TH2;

    // stage ker taps: 49 x 224, gmem-consecutive per tap
    const float* kerg = ker + (((size_t)b * GK + g * KK) * HW) + h0 * Wc;
    for (int i = tid; i < KS_FL; i += 256) {
        int idx = i / PIX;
        int pix = i - idx * PIX;
        ks[idx * PIX + pix] = kerg[(size_t)idx * HW + pix];
    }

    // stage x halo: 16 ch x 10 rows x 62 cols
    const float* xg = x + ((size_t)b * Cc + g * CG) * HW;
    for (int i = tid; i < CG * HR2 * HC2; i += 256) {
        int ch  = i / (HR2 * HC2);
        int rem = i - ch * (HR2 * HC2);
        int rr  = rem / HC2;
        int cc  = rem - rr * HC2;
        int gh  = h0 - 3 + rr;
        int gw  = cc - 3;
        float v = 0.f;
        if (gh >= 0 && gh < Hc && gw >= 0 && gw < Wc)
            v = xg[(size_t)ch * HW + gh * Wc + gw];
        xs[ch * XS_CH + rr * HP2 + cc] = v;
    }
    __syncthreads();

    if (tid < 224) {
        const int cg   = tid / 56;          // channel group 0..3
        const int q    = tid % 56;          // quad id
        const int r    = q / 14;            // local row 0..3
        const int col0 = (q % 14) * 4;      // first output col

        float acc[4][4];
#pragma unroll
        for (int c4 = 0; c4 < 4; c4++)
#pragma unroll
            for (int p = 0; p < 4; p++) acc[c4][p] = 0.f;

        const float* xbase = xs + (cg * 4) * XS_CH;
        const float* kbase = ks + r * Wc + col0;

#pragma unroll
        for (int i = 0; i < Kc; i++) {
            float win[4][10];
#pragma unroll
            for (int c4 = 0; c4 < 4; c4++) {
                const float* row = xbase + c4 * XS_CH + (r + i) * HP2 + col0;
                float4 w0 = *(const float4*)(row);
                float4 w1 = *(const float4*)(row + 4);
                float2 w2 = *(const float2*)(row + 8);
                win[c4][0] = w0.x; win[c4][1] = w0.y;
                win[c4][2] = w0.z; win[c4][3] = w0.w;
                win[c4][4] = w1.x; win[c4][5] = w1.y;
                win[c4][6] = w1.z; win[c4][7] = w1.w;
                win[c4][8] = w2.x; win[c4][9] = w2.y;
            }
#pragma unroll
            for (int j = 0; j < Kc; j++) {
                float4 kq = *(const float4*)(kbase + (i * Kc + j) * PIX);
#pragma unroll
                for (int c4 = 0; c4 < 4; c4++) {
                    acc[c4][0] += win[c4][j + 0] * kq.x;
                    acc[c4][1] += win[c4][j + 1] * kq.y;
                    acc[c4][2] += win[c4][j + 2] * kq.z;
                    acc[c4][3] += win[c4][j + 3] * kq.w;
                }
            }
        }

        float* ob = out + (((size_t)b * Cc + g * CG + cg * 4) * Hc
                           + (h0 + r)) * Wc + col0;
#pragma unroll
        for (int c4 = 0; c4 < 4; c4++)
            *(float4*)(ob + (size_t)c4 * HW) =
                make_float4(acc[c4][0], acc[c4][1], acc[c4][2], acc[c4][3]);
    }
}

// ---------------------------------------------------------------------------
// Launch
// ---------------------------------------------------------------------------
extern "C" void kernel_launch(void* const* d_in, const int* in_sizes, int n_in,
                              void* d_out, int out_size)
{
    const float* x        = (const float*)d_in[0];
    const float* reduce_w = (const float*)d_in[1];
    const float* reduce_b = (const float*)d_in[2];
    const float* bn_gamma = (const float*)d_in[3];
    const float* bn_beta  = (const float*)d_in[4];
    const float* bn_mean  = (const float*)d_in[5];
    const float* bn_var   = (const float*)d_in[6];
    const float* prelu_a  = (const float*)d_in[7];
    const float* span_w   = (const float*)d_in[8];
    const float* span_b   = (const float*)d_in[9];
    float* out = (float*)d_out;

    __half *xh, *xl, *th, *tl, *w1h, *w1l, *w2h, *w2l;
    float* ker_buf;
    cudaGetSymbolAddress((void**)&xh, g_xh);
    cudaGetSymbolAddress((void**)&xl, g_xl);
    cudaGetSymbolAddress((void**)&th, g_th);
    cudaGetSymbolAddress((void**)&tl, g_tl);
    cudaGetSymbolAddress((void**)&w1h, g_w1h);
    cudaGetSymbolAddress((void**)&w1l, g_w1l);
    cudaGetSymbolAddress((void**)&w2h, g_w2h);
    cudaGetSymbolAddress((void**)&w2l, g_w2l);
    cudaGetSymbolAddress((void**)&ker_buf, g_ker);

    cudaFuncSetAttribute(gemm_split_kernel<1>,
                         cudaFuncAttributeMaxDynamicSharedMemorySize, SMEM_TOT);
    cudaFuncSetAttribute(gemm_split_kernel<2>,
                         cudaFuncAttributeMaxDynamicSharedMemorySize, SMEM_TOT);
    cudaFuncSetAttribute(involution_kernel,
                         cudaFuncAttributeMaxDynamicSharedMemorySize, INV_SMEM);

    // 0) pre-split inputs
    {
        int n4 = Bc * Cc * HW / 4;
        split_kernel<<<(n4 + 255) / 256, 256>>>((const float4*)x,
                                                (uint2*)xh, (uint2*)xl, n4);
    }
    {
        int n4 = TNUM * Cc / 4;
        split_kernel<<<(n4 + 255) / 256, 256>>>((const float4*)reduce_w,
                                                (uint2*)w1h, (uint2*)w1l, n4);
    }
    {
        int n4 = GK * KDIM / 4;
        split_kernel<<<(n4 + 255) / 256, 256>>>((const float4*)span_w,
                                                (uint2*)w2h, (uint2*)w2l, n4);
    }

    // 1) GEMM1: T = BN_PReLU(reduce_w @ x), split output (feeds GEMM2)
    {
        dim3 grid(TNUM / BMg, HW / BNg, Bc);           // 2 x 49 x 4
        gemm_split_kernel<1><<<grid, 256, SMEM_TOT>>>(
            w1h, w1l, xh, xl,
            nullptr, th, tl,
            TNUM, HW,
            reduce_b, bn_gamma, bn_beta, bn_mean, bn_var, prelu_a);
    }
    // 2) GEMM2: KER = span_w @ T + span_b (fp32 out)
    {
        dim3 grid((GK + BMg - 1) / BMg, HW / BNg, Bc); // 7 x 49 x 4
        gemm_split_kernel<2><<<grid, 256, SMEM_TOT>>>(
            w2h, w2l, th, tl,
            ker_buf, nullptr, nullptr,
            GK, HW,
            span_b, nullptr, nullptr, nullptr, nullptr, nullptr);
    }
    // 3) involution aggregation (vectorized)
    {
        dim3 grid(Hc / TH2, Gc, Bc);                   // 14 x 16 x 4
        involution_kernel<<<grid, 256, INV_SMEM>>>(x, ker_buf, out);
    }
}

// round 17
// speedup vs baseline: 1.2082x; 1.2082x over previous
#include <cuda_runtime.h>
#include <cuda_fp16.h>
#include <cstdint>

// ---------------------------------------------------------------------------
// Problem constants
// ---------------------------------------------------------------------------
#define Bc    4
#define Cc    256
#define Hc    56
#define Wc    56
#define Gc    16
#define Kc    7
#define TNUM  256
#define HW    (Hc * Wc)          // 3136
#define CG    (Cc / Gc)          // 16
#define KK    (Kc * Kc)          // 49
#define GK    (Gc * KK)          // 784
#define EPSc  1e-5f
#define KDIM  256

// ---------------------------------------------------------------------------
// Scratch (no runtime allocation allowed)
// ---------------------------------------------------------------------------
__device__ __half g_xh[Bc * Cc * HW];
__device__ __half g_xl[Bc * Cc * HW];
__device__ __half g_th[Bc * TNUM * HW];   // T hi ONLY (lo dropped: 2-pass GEMM2)
__device__ __half g_w1h[TNUM * Cc];
__device__ __half g_w1l[TNUM * Cc];
__device__ __half g_w2h[GK * KDIM];
__device__ __half g_w2l[GK * KDIM];
__device__ float  g_ker[Bc * GK * HW];

// ---------------------------------------------------------------------------
// helpers
// ---------------------------------------------------------------------------
__device__ __forceinline__ void split2(float x, float y,
                                       uint32_t& hi, uint32_t& lo) {
    __half hx = __float2half_rn(x);
    __half hy = __float2half_rn(y);
    __half lx = __float2half_rn(x - __half2float(hx));
    __half ly = __float2half_rn(y - __half2float(hy));
    hi = (uint32_t)__half_as_ushort(hx) | ((uint32_t)__half_as_ushort(hy) << 16);
    lo = (uint32_t)__half_as_ushort(lx) | ((uint32_t)__half_as_ushort(ly) << 16);
}

__device__ __forceinline__ uint32_t pack_hi2(float x, float y) {
    __half hx = __float2half_rn(x);
    __half hy = __float2half_rn(y);
    return (uint32_t)__half_as_ushort(hx) | ((uint32_t)__half_as_ushort(hy) << 16);
}

__device__ __forceinline__ uint32_t smem_u32(const void* p) {
    uint32_t a;
    asm("{ .reg .u64 t; cvta.to.shared.u64 t, %1; cvt.u32.u64 %0, t; }"
        : "=r"(a) : "l"(p));
    return a;
}

// non-volatile — register-only, no side effects
#define MMA16816(Cr, Ar, B0, B1)                                           \
    asm("mma.sync.aligned.m16n8k16.row.col.f32.f16.f16.f32 "              \
        "{%0,%1,%2,%3}, {%4,%5,%6,%7}, {%8,%9}, {%0,%1,%2,%3};"           \
        : "+f"((Cr)[0]), "+f"((Cr)[1]), "+f"((Cr)[2]), "+f"((Cr)[3])       \
        : "r"((Ar)[0]), "r"((Ar)[1]), "r"((Ar)[2]), "r"((Ar)[3]),          \
          "r"(B0), "r"(B1))

#define LDSM4(R, addr)                                                     \
    asm volatile("ldmatrix.sync.aligned.m8n8.x4.shared.b16 "               \
        "{%0,%1,%2,%3}, [%4];"                                             \
        : "=r"((R)[0]), "=r"((R)[1]), "=r"((R)[2]), "=r"((R)[3])           \
        : "r"(addr))

#define LDSM4T(R, addr)                                                    \
    asm volatile("ldmatrix.sync.aligned.m8n8.x4.trans.shared.b16 "         \
        "{%0,%1,%2,%3}, [%4];"                                             \
        : "=r"((R)[0]), "=r"((R)[1]), "=r"((R)[2]), "=r"((R)[3])           \
        : "r"(addr))

#define CP_ASYNC16(dst, src, sz)                                           \
    asm volatile("cp.async.cg.shared.global [%0], [%1], 16, %2;"           \
        :: "r"(dst), "l"(src), "r"(sz))
#define CP_COMMIT() asm volatile("cp.async.commit_group;")

// ---------------------------------------------------------------------------
// Fused fp32 -> fp16 hi/lo split for all three inputs in ONE launch.
// ---------------------------------------------------------------------------
#define N4X  (Bc * Cc * HW / 4)      // 802816
#define N4W1 (TNUM * Cc / 4)         // 16384
#define N4W2 (GK * KDIM / 4)         // 50176
#define N4TOT (N4X + N4W1 + N4W2)

__global__ __launch_bounds__(256)
void split_all_kernel(const float4* __restrict__ sx,
                      const float4* __restrict__ sw1,
                      const float4* __restrict__ sw2)
{
    int i = blockIdx.x * blockDim.x + threadIdx.x;
    if (i >= N4TOT) return;
    const float4* src;
    uint2 *hi, *lo;
    int j = i;
    if (j < N4X) {
        src = sx;  hi = (uint2*)g_xh;  lo = (uint2*)g_xl;
    } else if ((j -= N4X) < N4W1) {
        src = sw1; hi = (uint2*)g_w1h; lo = (uint2*)g_w1l;
    } else {
        j -= N4W1;
        src = sw2; hi = (uint2*)g_w2h; lo = (uint2*)g_w2l;
    }
    float4 v = src[j];
    uint32_t h0, l0, h1, l1;
    split2(v.x, v.y, h0, l0);
    split2(v.z, v.w, h1, l1);
    hi[j] = make_uint2(h0, h1);
    lo[j] = make_uint2(l0, l1);
}

// ---------------------------------------------------------------------------
// Split-fp16 HMMA GEMM — R13 structure, templated on pass count.
// NPASS=3 (GEMM1): hh + hl + lh, B = hi+lo arrays, full ~1e-6 accuracy.
// NPASS=2 (GEMM2): hh + lh, B = hi array ONLY (T_lo dropped).
//   Error |w·T_lo| ~ 2^-11 rel (~1-4e-4 in norm) — inside the 1e-3 gate.
//   MMA volume x2/3, B bytes x1/2.
// Block: 256 thr (8 warps, 4Mx2N), tile 128x64, BK=32, 2-stage ring, 3 CTA/SM.
// ---------------------------------------------------------------------------
#define BMg 128
#define BNg 64
#define BKg 32
#define NCH (KDIM / BKg)          // 8
#define NST 2
#define PKA 40                    // A smem pitch (halves)
#define PKB 72                    // B smem pitch (halves)
#define A_BY (BMg * PKA * 2)      // 10240
#define B_BY (BKg * PKB * 2)      // 4608
#define STG3 (2 * A_BY + 2 * B_BY)    // 29696  (NPASS=3)
#define STG2 (2 * A_BY + 1 * B_BY)    // 25088  (NPASS=2)
#define SMEM3 (NST * STG3)            // 59392
#define SMEM2 (NST * STG2)            // 50176

template <int EPI, int NPASS>
__global__ __launch_bounds__(256, 3)
void gemm_split_kernel(const __half* __restrict__ Ahi,  // [M][K]
                       const __half* __restrict__ Alo,
                       const __half* __restrict__ Bhi,  // [batch][K][N]
                       const __half* __restrict__ Blo,  // null when NPASS==2
                       float* __restrict__ Cf,
                       __half* __restrict__ Chi,
                       int M, int Nfull,
                       const float* __restrict__ bias,
                       const float* __restrict__ gamma,
                       const float* __restrict__ beta,
                       const float* __restrict__ mean,
                       const float* __restrict__ var,
                       const float* __restrict__ prelu_a)
{
    constexpr int STG_BY = (NPASS == 3) ? STG3 : STG2;

    extern __shared__ __align__(16) char smem[];
    const uint32_t sbase = smem_u32(smem);

    const int tid  = threadIdx.x;
    const int lane = tid & 31;
    const int wid  = tid >> 5;
    const int wm   = wid & 3;
    const int wn   = wid >> 2;
    const int lane15 = lane & 15;
    const int hi8    = (lane & 16) >> 1;
    const int g    = lane >> 2;
    const int t2   = (lane & 3) * 2;

    const int rowBase = blockIdx.x * BMg;
    const int colBase = blockIdx.y * BNg;
    const int batch   = blockIdx.z;
    const __half* BhiP = Bhi + (size_t)batch * KDIM * Nfull;
    const __half* BloP = (NPASS == 3) ? Blo + (size_t)batch * KDIM * Nfull : nullptr;

    const int a_idx0 = tid;
    const int a_idx1 = tid + 256;
    const int b_kr = tid >> 3;
    const int b_nq = tid & 7;

    auto issue = [&](int ch, int s) {
        const int kc = ch * BKg;
        const uint32_t stg = sbase + s * STG_BY;
#pragma unroll
        for (int i = 0; i < 2; i++) {
            const int idx = i ? a_idx1 : a_idx0;
            const int row = idx >> 2;
            const int kq  = idx & 3;
            const int gm  = rowBase + row;
            const uint32_t sz = (gm < M) ? 16u : 0u;
            const int gmc = (gm < M) ? gm : 0;
            const uint32_t adst = stg + row * (PKA * 2) + kq * 16;
            const size_t  asrc = (size_t)gmc * KDIM + kc + kq * 8;
            CP_ASYNC16(adst,        Ahi + asrc, sz);
            CP_ASYNC16(adst + A_BY, Alo + asrc, sz);
        }
        const uint32_t bdst = stg + 2 * A_BY + b_kr * (PKB * 2) + b_nq * 16;
        const size_t  bsrc = (size_t)(kc + b_kr) * Nfull + colBase + b_nq * 8;
        CP_ASYNC16(bdst, BhiP + bsrc, 16u);
        if (NPASS == 3)
            CP_ASYNC16(bdst + B_BY, BloP + bsrc, 16u);
        CP_COMMIT();
    };

    float acc[2][4][4];
#pragma unroll
    for (int mt = 0; mt < 2; mt++)
#pragma unroll
        for (int nt = 0; nt < 4; nt++)
#pragma unroll
            for (int i = 0; i < 4; i++) acc[mt][nt][i] = 0.f;

    issue(0, 0);

    for (int c = 0; c < NCH; c++) {
        asm volatile("cp.async.wait_group 0;");
        __syncthreads();
        if (c + 1 < NCH) issue(c + 1, (c + 1) % NST);

        const int s = c % NST;
        const uint32_t aHiB = sbase + s * STG_BY;
        const uint32_t aLoB = aHiB + A_BY;
        const uint32_t bHiB = aHiB + 2 * A_BY;
        const uint32_t bLoB = bHiB + B_BY;      // valid only when NPASS==3

#pragma unroll
        for (int ks = 0; ks < 2; ks++) {
            const int k0 = ks * 16;
            uint32_t ah[2][4], al[2][4], bh[2][4], bl[2][4];
#pragma unroll
            for (int mt = 0; mt < 2; mt++) {
                int row = wm * 32 + mt * 16 + lane15;
                uint32_t off = row * (PKA * 2) + (k0 + hi8) * 2;
                LDSM4(ah[mt], aHiB + off);
                LDSM4(al[mt], aLoB + off);
            }
#pragma unroll
            for (int nb = 0; nb < 2; nb++) {
                int nn   = wn * 32 + nb * 16 + hi8;
                int krow = k0 + lane15;
                uint32_t off = krow * (PKB * 2) + nn * 2;
                LDSM4T(bh[nb], bHiB + off);
                if (NPASS == 3) LDSM4T(bl[nb], bLoB + off);
            }
            // pass 1: hi*hi — 8 MMAs to different accumulators
#pragma unroll
            for (int nb = 0; nb < 2; nb++)
#pragma unroll
                for (int ng = 0; ng < 2; ng++)
#pragma unroll
                    for (int mt = 0; mt < 2; mt++)
                        MMA16816(acc[mt][nb * 2 + ng], ah[mt],
                                 bh[nb][2 * ng], bh[nb][2 * ng + 1]);
            // pass 2: hi*lo (NPASS==3 only)
            if (NPASS == 3) {
#pragma unroll
                for (int nb = 0; nb < 2; nb++)
#pragma unroll
                    for (int ng = 0; ng < 2; ng++)
#pragma unroll
                        for (int mt = 0; mt < 2; mt++)
                            MMA16816(acc[mt][nb * 2 + ng], ah[mt],
                                     bl[nb][2 * ng], bl[nb][2 * ng + 1]);
            }
            // pass 3: lo*hi
#pragma unroll
            for (int nb = 0; nb < 2; nb++)
#pragma unroll
                for (int ng = 0; ng < 2; ng++)
#pragma unroll
                    for (int mt = 0; mt < 2; mt++)
                        MMA16816(acc[mt][nb * 2 + ng], al[mt],
                                 bh[nb][2 * ng], bh[nb][2 * ng + 1]);
        }
    }

    // ---- epilogue (N always in-bounds: 3136 % 64 == 0) ----
#pragma unroll
    for (int mt = 0; mt < 2; mt++) {
        int r0 = rowBase + wm * 32 + mt * 16 + g;
#pragma unroll
        for (int half_ = 0; half_ < 2; half_++) {
            int rr = r0 + half_ * 8;
            if (rr >= M) continue;
            float bb = bias[rr];
            float sc = 0.f, mn = 0.f, bt = 0.f, aa = 0.f;
            if (EPI == 1) {
                sc = gamma[rr] * rsqrtf(var[rr] + EPSc);
                mn = mean[rr];
                bt = beta[rr];
                aa = prelu_a[0];
            }
#pragma unroll
            for (int nt = 0; nt < 4; nt++) {
                int col = colBase + wn * 32 + nt * 8 + t2;
                float v0 = acc[mt][nt][half_ * 2 + 0] + bb;
                float v1 = acc[mt][nt][half_ * 2 + 1] + bb;
                if (EPI == 1) {
                    v0 = (v0 - mn) * sc + bt;
                    v1 = (v1 - mn) * sc + bt;
                    v0 = v0 > 0.f ? v0 : aa * v0;
                    v1 = v1 > 0.f ? v1 : aa * v1;
                    size_t idx = ((size_t)batch * M + rr) * Nfull + col;
                    *(uint32_t*)(Chi + idx) = pack_hi2(v0, v1);   // hi only
                } else {
                    size_t idx = ((size_t)batch * M + rr) * Nfull + col;
                    *(float2*)(Cf + idx) = make_float2(v0, v1);
                }
            }
        }
    }
}

// ---------------------------------------------------------------------------
// Involution aggregation — R13/R7 one-barrier version (best known), verbatim.
// ---------------------------------------------------------------------------
#define TH 4
#define HALO_R (TH + 6)           // 10
#define HALO_C 62
#define HALO_P 64                 // smem pitch

__global__ __launch_bounds__(256)
void involution_kernel(const float* __restrict__ x,
                       const float* __restrict__ ker,
                       float* __restrict__ out)
{
    __shared__ float xs[CG][HALO_R][HALO_P];   // 40 KB

    const int tileRow = blockIdx.x;
    const int g = blockIdx.y;
    const int b = blockIdx.z;
    const int tid = threadIdx.x;

    const int h0 = tileRow * TH;
    const bool active = tid < TH * Wc;          // 224
    const int r  = tid / Wc;
    const int cw = tid % Wc;
    const int h  = h0 + r;

    float kreg[KK];
    if (active) {
        const float* kp = ker + (((size_t)b * GK + g * KK) * HW) + h * Wc + cw;
#pragma unroll
        for (int idx = 0; idx < KK; idx++) kreg[idx] = kp[(size_t)idx * HW];
    }

    const float* xg = x + ((size_t)b * Cc + g * CG) * HW;
    for (int i = tid; i < CG * HALO_R * HALO_C; i += 256) {
        int ch  = i / (HALO_R * HALO_C);
        int rem = i - ch * (HALO_R * HALO_C);
        int rr  = rem / HALO_C;
        int cc  = rem - rr * HALO_C;
        int gh  = h0 - 3 + rr;
        int gw  = cc - 3;
        float v = 0.f;
        if (gh >= 0 && gh < Hc && gw >= 0 && gw < Wc)
            v = xg[(size_t)ch * HW + gh * Wc + gw];
        xs[ch][rr][cc] = v;
    }
    __syncthreads();

    if (active) {
        float* op = out + (((size_t)b * Cc + g * CG) * Hc + h) * Wc + cw;
#pragma unroll 4
        for (int ci = 0; ci < CG; ci++) {
            float a = 0.f;
#pragma unroll
            for (int i = 0; i < Kc; i++)
#pragma unroll
                for (int j = 0; j < Kc; j++)
                    a += xs[ci][r + i][cw + j] * kreg[i * Kc + j];
            op[(size_t)ci * HW] = a;
        }
    }
}

// ---------------------------------------------------------------------------
// Launch
// ---------------------------------------------------------------------------
extern "C" void kernel_launch(void* const* d_in, const int* in_sizes, int n_in,
                              void* d_out, int out_size)
{
    const float* x        = (const float*)d_in[0];
    const float* reduce_w = (const float*)d_in[1];
    const float* reduce_b = (const float*)d_in[2];
    const float* bn_gamma = (const float*)d_in[3];
    const float* bn_beta  = (const float*)d_in[4];
    const float* bn_mean  = (const float*)d_in[5];
    const float* bn_var   = (const float*)d_in[6];
    const float* prelu_a  = (const float*)d_in[7];
    const float* span_w   = (const float*)d_in[8];
    const float* span_b   = (const float*)d_in[9];
    float* out = (float*)d_out;

    __half *xh, *xl, *th, *w1h, *w1l, *w2h, *w2l;
    float* ker_buf;
    cudaGetSymbolAddress((void**)&xh, g_xh);
    cudaGetSymbolAddress((void**)&xl, g_xl);
    cudaGetSymbolAddress((void**)&th, g_th);
    cudaGetSymbolAddress((void**)&w1h, g_w1h);
    cudaGetSymbolAddress((void**)&w1l, g_w1l);
    cudaGetSymbolAddress((void**)&w2h, g_w2h);
    cudaGetSymbolAddress((void**)&w2l, g_w2l);
    cudaGetSymbolAddress((void**)&ker_buf, g_ker);

    cudaFuncSetAttribute((const void*)gemm_split_kernel<1, 3>,
                         cudaFuncAttributeMaxDynamicSharedMemorySize, SMEM3);
    cudaFuncSetAttribute((const void*)gemm_split_kernel<2, 2>,
                         cudaFuncAttributeMaxDynamicSharedMemorySize, SMEM2);

    // 0) pre-split all inputs (single launch)
    split_all_kernel<<<(N4TOT + 255) / 256, 256>>>(
        (const float4*)x, (const float4*)reduce_w, (const float4*)span_w);

    // 1) GEMM1: T = BN_PReLU(reduce_w @ x), hi-only output (feeds GEMM2)
    {
        dim3 grid(TNUM / BMg, HW / BNg, Bc);           // 2 x 49 x 4
        gemm_split_kernel<1, 3><<<grid, 256, SMEM3>>>(
            w1h, w1l, xh, xl,
            nullptr, th,
            TNUM, HW,
            reduce_b, bn_gamma, bn_beta, bn_mean, bn_var, prelu_a);
    }
    // 2) GEMM2: KER = span_w @ T_hi + span_b (2-pass, fp32 out)
    {
        dim3 grid((GK + BMg - 1) / BMg, HW / BNg, Bc); // 7 x 49 x 4
        gemm_split_kernel<2, 2><<<grid, 256, SMEM2>>>(
            w2h, w2l, th, nullptr,
            ker_buf, nullptr,
            GK, HW,
            span_b, nullptr, nullptr, nullptr, nullptr, nullptr);
    }
    // 3) involution aggregation
    {
        dim3 grid(Hc / TH, Gc, Bc);
        involution_kernel<<<grid, 256>>>(x, ker_buf, out);
    }
}